// round 4
// baseline (speedup 1.0000x reference)
#include <cuda_runtime.h>

// -------------------------------------------------------------------------
// MaskedBilinearFullSymLoss — B=16, C=2, H=W=512, scalar f32 output.
// Vectorized: each thread handles a quad of 4 consecutive pixels per row,
// float4 loads; shifted rows load 2 aligned float4s with a compile-time
// window offset O = (shift & 3), dispatched per-block (uniform).
// -------------------------------------------------------------------------

#define HH 512
#define WW 512
#define RPB 4           // rows per block
#define TXV 125         // tx < TXV -> vector path (all loads provably in-bounds)

__device__ double g_acc;            // zero-initialized
__device__ unsigned int g_ticket;   // zero-initialized

struct F8 { float v[8]; };

__device__ __forceinline__ F8 load8(const float* __restrict__ p) {
    float4 a = *(const float4*)p;
    float4 b = *(const float4*)(p + 4);
    F8 r;
    r.v[0] = a.x; r.v[1] = a.y; r.v[2] = a.z; r.v[3] = a.w;
    r.v[4] = b.x; r.v[5] = b.y; r.v[6] = b.z; r.v[7] = b.w;
    return r;
}

struct Ctx {
    const float* __restrict__ g0;
    const float* __restrict__ g1;
    const float* __restrict__ mk;
    int dx1, dy1, dy2, imax, jmax;
    float wx1, wx2, wy1, wy2, w11, w12, w21, w22;
    float sym_x, sym_y;
};

// ---------------- positive branch (dx > 0) ----------------

template<int O>
__device__ __forceinline__ float pos_quad_vec(const Ctx& c, int i, int tx, float rv) {
    const int c0 = 4 * tx;
    const int sb = c0 + (c.dx1 - O);          // aligned shifted base
    const float* g0a = c.g0 + (size_t)(i + c.dy1) * WW;
    const float* g0b = c.g0 + (size_t)(i + c.dy2) * WW;
    const float* g1a = c.g1 + (size_t)(i + c.dy1) * WW;
    const float* g1b = c.g1 + (size_t)(i + c.dy2) * WW;
    F8 A0 = load8(g0a + sb), B0 = load8(g0b + sb);
    F8 A1 = load8(g1a + sb), B1 = load8(g1b + sb);
    float4 r0 = *(const float4*)(c.g0 + (size_t)i * WW + c0);
    float4 r1 = *(const float4*)(c.g1 + (size_t)i * WW + c0);
    float4 mq = *(const float4*)(c.mk + (size_t)i * WW + c0);
    float rr0[4] = {r0.x, r0.y, r0.z, r0.w};
    float rr1[4] = {r1.x, r1.y, r1.z, r1.w};
    float mv[4]  = {mq.x, mq.y, mq.z, mq.w};
    float acc = 0.f;
    #pragma unroll
    for (int k = 0; k < 4; k++) {
        float s0 = c.w11 * A0.v[O+k] + c.w12 * A0.v[O+k+1]
                 + c.w21 * B0.v[O+k] + c.w22 * B0.v[O+k+1];
        float s1 = c.w11 * A1.v[O+k] + c.w12 * A1.v[O+k+1]
                 + c.w21 * B1.v[O+k] + c.w22 * B1.v[O+k+1];
        float err = (rr0[k] - s0) * c.sym_y + (rr1[k] - s1) * c.sym_x;
        float val = (c0 + k < c.jmax) ? rv : 0.f;
        acc += val * mv[k] * err * err;
    }
    return acc;
}

__device__ __forceinline__ float pos_quad_scalar(const Ctx& c, int i, int tx, float rv) {
    const float* g0r = c.g0 + (size_t)i * WW;
    const float* g1r = c.g1 + (size_t)i * WW;
    const float* g0a = c.g0 + (size_t)(i + c.dy1) * WW;
    const float* g0b = c.g0 + (size_t)(i + c.dy2) * WW;
    const float* g1a = c.g1 + (size_t)(i + c.dy1) * WW;
    const float* g1b = c.g1 + (size_t)(i + c.dy2) * WW;
    const float* mr  = c.mk + (size_t)i * WW;
    float acc = 0.f;
    #pragma unroll
    for (int k = 0; k < 4; k++) {
        const int j = 4 * tx + k;
        if (j < c.jmax) {
            const int ja = j + c.dx1, jb = ja + 1;
            float s0 = c.w11 * g0a[ja] + c.w12 * g0a[jb]
                     + c.w21 * g0b[ja] + c.w22 * g0b[jb];
            float s1 = c.w11 * g1a[ja] + c.w12 * g1a[jb]
                     + c.w21 * g1b[ja] + c.w22 * g1b[jb];
            float err = (g0r[j] - s0) * c.sym_y + (g1r[j] - s1) * c.sym_x;
            acc += rv * mr[j] * err * err;
        }
    }
    return acc;
}

template<int O>
__device__ __forceinline__ float run_pos(const Ctx& c, int i0, int tx, int ty) {
    float acc = 0.f;
    #pragma unroll
    for (int it = 0; it < RPB / 2; it++) {
        const int i = i0 + ty + 2 * it;
        const float rv = (i < c.imax) ? 1.f : 0.f;
        const int ie = min(i, c.imax - 1);
        if (tx < TXV) acc += pos_quad_vec<O>(c, ie, tx, rv);
        else          acc += pos_quad_scalar(c, ie, tx, rv);
    }
    return acc;
}

// ---------------- negative branch (dx <= 0) ----------------
// delta_c = [wx1*g_c(i+dy2, j) + wx2*g_c(i+dy2, min(j+1,W-1))]
//         - [wy1*g_c(i+1, j-dx1) + wy2*g_c(i, j-dx1)]
// mask at (i+dy2, j-dx1), valid j < W+dx1.

template<int O2>
__device__ __forceinline__ float neg_quad_vec(const Ctx& c, int i, int tx, float rv) {
    const int c0 = 4 * tx;
    const int m2 = -c.dx1;
    const int sb = c0 + (m2 - O2);            // aligned shifted base
    const float* g0A  = c.g0 + (size_t)(i + c.dy2) * WW;
    const float* g1A  = c.g1 + (size_t)(i + c.dy2) * WW;
    const float* g0s1 = c.g0 + (size_t)(i + 1) * WW;
    const float* g0s2 = c.g0 + (size_t)i * WW;
    const float* g1s1 = c.g1 + (size_t)(i + 1) * WW;
    const float* g1s2 = c.g1 + (size_t)i * WW;
    const float* mA   = c.mk + (size_t)(i + c.dy2) * WW;

    float4 a0 = *(const float4*)(g0A + c0); float a0e = g0A[c0 + 4];
    float4 a1 = *(const float4*)(g1A + c0); float a1e = g1A[c0 + 4];
    F8 S0a = load8(g0s1 + sb), S0b = load8(g0s2 + sb);
    F8 S1a = load8(g1s1 + sb), S1b = load8(g1s2 + sb);
    F8 MM  = load8(mA + sb);
    float A0v[5] = {a0.x, a0.y, a0.z, a0.w, a0e};
    float A1v[5] = {a1.x, a1.y, a1.z, a1.w, a1e};
    float acc = 0.f;
    #pragma unroll
    for (int k = 0; k < 4; k++) {
        float f0 = c.wx1 * A0v[k] + c.wx2 * A0v[k+1];
        float f1 = c.wx1 * A1v[k] + c.wx2 * A1v[k+1];
        float s0 = c.wy1 * S0a.v[O2+k] + c.wy2 * S0b.v[O2+k];
        float s1 = c.wy1 * S1a.v[O2+k] + c.wy2 * S1b.v[O2+k];
        float err = (f0 - s0) * c.sym_y + (f1 - s1) * c.sym_x;
        float val = (c0 + k < c.jmax) ? rv : 0.f;
        acc += val * MM.v[O2+k] * err * err;
    }
    return acc;
}

__device__ __forceinline__ float neg_quad_scalar(const Ctx& c, int i, int tx, float rv) {
    const float* g0A  = c.g0 + (size_t)(i + c.dy2) * WW;
    const float* g1A  = c.g1 + (size_t)(i + c.dy2) * WW;
    const float* g0s1 = c.g0 + (size_t)(i + 1) * WW;
    const float* g0s2 = c.g0 + (size_t)i * WW;
    const float* g1s1 = c.g1 + (size_t)(i + 1) * WW;
    const float* g1s2 = c.g1 + (size_t)i * WW;
    const float* mA   = c.mk + (size_t)(i + c.dy2) * WW;
    float acc = 0.f;
    #pragma unroll
    for (int k = 0; k < 4; k++) {
        const int j = 4 * tx + k;
        if (j < c.jmax) {
            const int cB = j - c.dx1;
            const int c1 = min(j + 1, WW - 1);
            float f0 = c.wx1 * g0A[j] + c.wx2 * g0A[c1];
            float f1 = c.wx1 * g1A[j] + c.wx2 * g1A[c1];
            float s0 = c.wy1 * g0s1[cB] + c.wy2 * g0s2[cB];
            float s1 = c.wy1 * g1s1[cB] + c.wy2 * g1s2[cB];
            float err = (f0 - s0) * c.sym_y + (f1 - s1) * c.sym_x;
            acc += rv * mA[cB] * err * err;
        }
    }
    return acc;
}

template<int O2>
__device__ __forceinline__ float run_neg(const Ctx& c, int i0, int tx, int ty) {
    float acc = 0.f;
    #pragma unroll
    for (int it = 0; it < RPB / 2; it++) {
        const int i = i0 + ty + 2 * it;
        const float rv = (i < c.imax) ? 1.f : 0.f;
        const int ie = min(i, c.imax - 1);
        if (tx < TXV) acc += neg_quad_vec<O2>(c, ie, tx, rv);
        else          acc += neg_quad_scalar(c, ie, tx, rv);
    }
    return acc;
}

// ---------------- kernel ----------------

__global__ __launch_bounds__(256, 4)
void loss_kernel(const float* __restrict__ grid,
                 const float* __restrict__ gt,
                 const float* __restrict__ gd,
                 const float* __restrict__ mask,
                 int B, unsigned int nblocks, float* __restrict__ out)
{
    const int H = HH, W = WW;
    const int b  = blockIdx.y;
    const int i0 = blockIdx.x * RPB;
    const int tid = threadIdx.x;
    const int tx = tid & 127;      // quad index within row (4*tx..4*tx+3)
    const int ty = tid >> 7;       // row sub-index

    const float dx = -8.0f * gt[2 * b + 0];
    const float dy =  8.0f * gt[2 * b + 1];

    Ctx c;
    c.sym_x = gd[2 * b + 0];
    c.sym_y = gd[2 * b + 1];
    const float dx1f = floorf(dx), dy1f = floorf(dy);
    c.dx1 = (int)dx1f;  c.dy1 = (int)dy1f;  c.dy2 = c.dy1 + 1;
    const int dx2 = c.dx1 + 1;
    c.wx1 = (dx1f + 1.0f) - dx;  c.wx2 = dx - dx1f;
    c.wy1 = (dy1f + 1.0f) - dy;  c.wy2 = dy - dy1f;
    c.w11 = c.wy1 * c.wx1;  c.w12 = c.wy1 * c.wx2;
    c.w21 = c.wy2 * c.wx1;  c.w22 = c.wy2 * c.wx2;
    c.g0 = grid + (size_t)(2 * b + 0) * H * W;
    c.g1 = grid + (size_t)(2 * b + 1) * H * W;
    c.mk = mask + (size_t)b * H * W;
    c.imax = H - c.dy2;

    float acc;
    float cnt;
    if (dx > 0.0f) {
        c.jmax = W - dx2;
        cnt = (float)c.imax * (float)c.jmax;
        switch (c.dx1 & 3) {
            case 0:  acc = run_pos<0>(c, i0, tx, ty); break;
            case 1:  acc = run_pos<1>(c, i0, tx, ty); break;
            case 2:  acc = run_pos<2>(c, i0, tx, ty); break;
            default: acc = run_pos<3>(c, i0, tx, ty); break;
        }
    } else {
        c.jmax = W + c.dx1;
        cnt = (float)c.imax * (float)c.jmax;
        switch ((-c.dx1) & 3) {
            case 0:  acc = run_neg<0>(c, i0, tx, ty); break;
            case 1:  acc = run_neg<1>(c, i0, tx, ty); break;
            case 2:  acc = run_neg<2>(c, i0, tx, ty); break;
            default: acc = run_neg<3>(c, i0, tx, ty); break;
        }
    }

    // ---- block reduction
    #pragma unroll
    for (int o = 16; o > 0; o >>= 1)
        acc += __shfl_down_sync(0xFFFFFFFFu, acc, o);

    __shared__ float wsum[8];
    const int lane = tid & 31;
    const int warp = tid >> 5;
    if (lane == 0) wsum[warp] = acc;
    __syncthreads();

    if (tid == 0) {
        float s = 0.0f;
        #pragma unroll
        for (int k = 0; k < 8; k++) s += wsum[k];
        double scaled = (double)s / ((double)cnt * (double)B);
        atomicAdd(&g_acc, scaled);

        __threadfence();
        unsigned int prev = atomicInc(&g_ticket, nblocks - 1u);
        if (prev == nblocks - 1u) {
            double total = atomicAdd(&g_acc, 0.0);   // atomic read
            out[0] = (float)total;
            g_acc = 0.0;                              // reset for next replay
            __threadfence();
        }
    }
}

extern "C" void kernel_launch(void* const* d_in, const int* in_sizes, int n_in,
                              void* d_out, int out_size)
{
    const float* grid = (const float*)d_in[0];
    const float* gt   = (const float*)d_in[1];
    const float* gd   = (const float*)d_in[2];
    const float* mask = (const float*)d_in[3];
    float* out = (float*)d_out;

    const int B = in_sizes[1] / 2;   // gt_sym_axis is (B, 2)

    dim3 g(HH / RPB, B);
    unsigned int nblocks = (HH / RPB) * B;
    loss_kernel<<<g, 256>>>(grid, gt, gd, mask, B, nblocks, out);
}